// round 15
// baseline (speedup 1.0000x reference)
#include <cuda_runtime.h>
#include <cuda_bf16.h>
#include <cstdint>

// 3x3 median filter, zero padding, exact median of 9.
// x: (32, 3, 512, 512) fp32 -> 96 images of 512x512.
//
// Persistent blocks + cp.async.bulk double-buffered pipeline, sized for
// guaranteed 5-block/SM residency:
//   - bulk copy = the strip's own 8 rows only (16KB, always in-bounds)
//   - the 2 halo rows come from per-thread gmem loads issued BEFORE the
//     mbarrier wait (latency overlaps the wait)
//   - 2x16KB buffers -> 32.1KB static smem/block; carveout forced to max.
// Compute = round-10 exact network (pair-shared sort2 of middle rows,
// pair-shared sliding windows, ~16 FMNMX/px), masks on the fma pipe,
// streaming stores.

#define W 512
#define H 512
#define NIMG 96
#define SMROWS 8
#define CPBYTES (SMROWS * W * 4)   // 16384
#define NSTRIPS (NIMG * (H / 8))   // 6144
#define GRID 740                   // 5 blocks/SM * 148 SMs

__device__ __forceinline__ uint32_t s2u(const void* p) {
    uint32_t a;
    asm("{ .reg .u64 t; cvta.to.shared.u64 t, %1; cvt.u32.u64 %0, t; }"
        : "=r"(a) : "l"(p));
    return a;
}
__device__ __forceinline__ void mbar_init(uint32_t a, uint32_t n) {
    asm volatile("mbarrier.init.shared.b64 [%0], %1;" :: "r"(a), "r"(n) : "memory");
}
__device__ __forceinline__ void mbar_expect(uint32_t a, uint32_t bytes) {
    asm volatile("mbarrier.arrive.expect_tx.shared.b64 _, [%0], %1;"
                 :: "r"(a), "r"(bytes) : "memory");
}
__device__ __forceinline__ void bulk_ld(uint32_t dst, const float* src, uint32_t mbar) {
    asm volatile(
        "cp.async.bulk.shared::cta.global.mbarrier::complete_tx::bytes [%0], [%1], %2, [%3];"
        :: "r"(dst), "l"(src), "r"((uint32_t)CPBYTES), "r"(mbar) : "memory");
}
__device__ __forceinline__ void mbar_wait(uint32_t a, uint32_t parity) {
    asm volatile(
        "{\n\t"
        ".reg .pred P;\n\t"
        "WL_%=:\n\t"
        "mbarrier.try_wait.parity.acquire.cta.shared::cta.b64 P, [%0], %1, 0x989680;\n\t"
        "@!P bra WL_%=;\n\t"
        "}"
        :: "r"(a), "r"(parity) : "memory");
}

__device__ __forceinline__ float med3(float a, float b, float c) {
    return fmaxf(fminf(a, b), fminf(fmaxf(a, b), c));
}

// 6-col window from a shared-memory row (interior rows: only col masks).
__device__ __forceinline__ void srow_n(const float* __restrict__ rp,
                                       int cb, int cl, int cr,
                                       float ml, float mr, float* c) {
    const float4 v = *reinterpret_cast<const float4*>(rp + cb);
    c[0] = rp[cl] * ml;
    c[1] = v.x; c[2] = v.y; c[3] = v.z; c[4] = v.w;
    c[5] = rp[cr] * mr;
}

// Emit one output row: insert row a into (mn, mx) = sort2 of the other two
// rows, combine 3-wide windows with pair sharing, streaming-store a float4.
__device__ __forceinline__ void emit_row(const float* a, const float* mn,
                                         const float* mx,
                                         float* __restrict__ outp) {
    float lo[6], mi[6], hi[6];
    #pragma unroll
    for (int i = 0; i < 6; i++) {
        lo[i] = fminf(a[i], mn[i]);
        hi[i] = fmaxf(a[i], mx[i]);
        mi[i] = fmaxf(mn[i], fminf(a[i], mx[i]));
    }
    float o[4];
    #pragma unroll
    for (int t = 0; t < 2; t++) {
        const int i = 2 * t + 1;
        const float A = fmaxf(lo[i], lo[i + 1]);
        const float B = fminf(hi[i], hi[i + 1]);
        const float n = fminf(mi[i], mi[i + 1]);
        const float m = fmaxf(mi[i], mi[i + 1]);
        o[2 * t]     = med3(fmaxf(A, lo[2 * t]),
                            fmaxf(n, fminf(m, mi[2 * t])),
                            fminf(B, hi[2 * t]));
        o[2 * t + 1] = med3(fmaxf(A, lo[2 * t + 3]),
                            fminf(m, fmaxf(n, mi[2 * t + 3])),
                            fminf(B, hi[2 * t + 3]));
    }
    float4 res; res.x = o[0]; res.y = o[1]; res.z = o[2]; res.w = o[3];
    __stcs(reinterpret_cast<float4*>(outp), res);
}

__global__ void __launch_bounds__(256, 5)
median3x3_kernel(const float* __restrict__ x, float* __restrict__ out) {
    __shared__ __align__(16) float sb[2][SMROWS * W];   // 32 KB
    __shared__ __align__(8) unsigned long long mbar_s[2];

    const int tid = threadIdx.x;
    const uint32_t mb0 = s2u(&mbar_s[0]), mb1 = s2u(&mbar_s[1]);
    const uint32_t sb0 = s2u(&sb[0][0]), sb1 = s2u(&sb[1][0]);

    if (tid == 0) {
        mbar_init(mb0, 1);
        mbar_init(mb1, 1);
        asm volatile("fence.proxy.async.shared::cta;" ::: "memory");
    }
    __syncthreads();

    const int cb = (tid & 127) << 2;    // column base 0..508
    const int h  = tid >> 7;            // row half 0/1 (warp-uniform)
    const int cl = (cb == 0)     ? 0     : cb - 1;
    const int cr = (cb == W - 4) ? W - 1 : cb + 4;
    const float ml = (cb > 0)     ? 1.0f : 0.0f;
    const float mr = (cb < W - 4) ? 1.0f : 0.0f;

    int s = blockIdx.x;
    if (tid == 0) {
        mbar_expect(mb0, CPBYTES);
        bulk_ld(sb0, x + (s >> 6) * (H * W) + ((s & 63) << 3) * W, mb0);
    }

    int it = 0;
    for (; s < NSTRIPS; s += GRID, it++) {
        const int buf = it & 1;
        const int nxt = s + GRID;
        const int img = s >> 6;
        const int y0  = (s & 63) << 3;

        // Halo row straight from gmem — issued before the wait so its
        // latency overlaps the mbarrier wait / prefetch.
        float redge[6];
        {
            const int ey    = (h == 0) ? max(y0 - 1, 0) : min(y0 + 8, H - 1);
            const float me  = (h == 0) ? ((y0 > 0) ? 1.0f : 0.0f)
                                       : ((y0 < H - 8) ? 1.0f : 0.0f);
            const float* rp = x + img * (H * W) + ey * W;
            const float4 v  = *reinterpret_cast<const float4*>(rp + cb);
            redge[0] = __ldg(rp + cl) * (ml * me);
            redge[1] = v.x * me; redge[2] = v.y * me;
            redge[3] = v.z * me; redge[4] = v.w * me;
            redge[5] = __ldg(rp + cr) * (mr * me);
        }

        if (it > 0) __syncthreads();          // other buffer free to overwrite
        if (tid == 0 && nxt < NSTRIPS) {
            mbar_expect(buf ? mb0 : mb1, CPBYTES);
            bulk_ld(buf ? sb0 : sb1,
                    x + (nxt >> 6) * (H * W) + ((nxt & 63) << 3) * W,
                    buf ? mb0 : mb1);
        }

        mbar_wait(buf ? mb1 : mb0, (it >> 1) & 1);

        const float* S = buf ? sb[1] : sb[0];
        float ra[6], rb[6], rc[6], rd[6], re[6], rf[6];
        float mn[6], mx[6];

        const int yb = y0 + (h << 2);
        float* op = out + img * (H * W) + yb * W + cb;

        if (h == 0) {
            // pair0 inputs: (y0-1[gmem], y0, y0+1, y0+2); pair1: +(y0+3, y0+4)
            #pragma unroll
            for (int i = 0; i < 6; i++) ra[i] = redge[i];
            srow_n(S,         cb, cl, cr, ml, mr, rb);
            srow_n(S + W,     cb, cl, cr, ml, mr, rc);
            srow_n(S + 2 * W, cb, cl, cr, ml, mr, rd);
            srow_n(S + 3 * W, cb, cl, cr, ml, mr, re);
            srow_n(S + 4 * W, cb, cl, cr, ml, mr, rf);
        } else {
            // pair0 inputs: (y0+3, y0+4, y0+5, y0+6); pair1: +(y0+7, y0+8[gmem])
            srow_n(S + 3 * W, cb, cl, cr, ml, mr, ra);
            srow_n(S + 4 * W, cb, cl, cr, ml, mr, rb);
            srow_n(S + 5 * W, cb, cl, cr, ml, mr, rc);
            srow_n(S + 6 * W, cb, cl, cr, ml, mr, rd);
            srow_n(S + 7 * W, cb, cl, cr, ml, mr, re);
            #pragma unroll
            for (int i = 0; i < 6; i++) rf[i] = redge[i];
        }

        // pair 0: outputs yb, yb+1
        #pragma unroll
        for (int i = 0; i < 6; i++) {
            mn[i] = fminf(rb[i], rc[i]);
            mx[i] = fmaxf(rb[i], rc[i]);
        }
        emit_row(ra, mn, mx, op);
        emit_row(rd, mn, mx, op + W);

        // pair 1: outputs yb+2, yb+3
        #pragma unroll
        for (int i = 0; i < 6; i++) {
            mn[i] = fminf(rd[i], re[i]);
            mx[i] = fmaxf(rd[i], re[i]);
        }
        emit_row(rc, mn, mx, op + 2 * W);
        emit_row(rf, mn, mx, op + 3 * W);
    }
}

extern "C" void kernel_launch(void* const* d_in, const int* in_sizes, int n_in,
                              void* d_out, int out_size) {
    const float* x = (const float*)d_in[0];
    float* out = (float*)d_out;

    // Belt-and-braces: request maximum L1/smem carveout so 5 blocks/SM
    // (5 x 32.1KB) are always co-resident. Idempotent; safe under capture.
    cudaFuncSetAttribute(median3x3_kernel,
                         cudaFuncAttributePreferredSharedMemoryCarveout, 100);

    median3x3_kernel<<<GRID, 256>>>(x, out);
}

// round 16
// speedup vs baseline: 1.1039x; 1.1039x over previous
#include <cuda_runtime.h>
#include <cuda_bf16.h>

// 3x3 median filter, zero padding, exact median of 9.
// x: (32, 3, 512, 512) fp32 -> 96 images of 512x512.
//
// Round-10 structure (best: 33.8us kernel): thread = 4 cols x 4 output
// rows, register-resident, two load batches, shared sort2 of middle rows,
// pair-shared sliding-window combine, exact min/max network, streaming
// stores, 128-thread blocks (10/SM).
// New: block-uniform interior/boundary specialization. Interior strips
// (126/128) skip all row clamps and row-mask FMULs and use immediate-
// offset addressing off one base pointer. Boundary strips keep the
// proven masked path. One launch, no divergence (block == strip).

#define W 512
#define H 512
#define NIMG 96

__device__ __forceinline__ float med3(float a, float b, float c) {
    return fmaxf(fminf(a, b), fminf(fmaxf(a, b), c));
}

// Load one row's 6-column window (cb-1 .. cb+4). MASK_ROW applies the
// vertical zero-pad mask mrow (exact 0/1 FMUL on the fma pipe).
template <bool MASK_ROW>
__device__ __forceinline__ void load_row(const float* __restrict__ rowp,
                                         int cb, int cl, int cr,
                                         float ml, float mr, float mrow,
                                         float* c) {
    const float4 v = *reinterpret_cast<const float4*>(rowp + cb);
    const float l = __ldg(rowp + cl);
    const float r = __ldg(rowp + cr);
    if (MASK_ROW) {
        c[0] = l * (ml * mrow);
        c[1] = v.x * mrow; c[2] = v.y * mrow;
        c[3] = v.z * mrow; c[4] = v.w * mrow;
        c[5] = r * (mr * mrow);
    } else {
        c[0] = l * ml;
        c[1] = v.x; c[2] = v.y; c[3] = v.z; c[4] = v.w;
        c[5] = r * mr;
    }
}

// Emit one output row: insert row a into (mn, mx) = sort2 of the other two
// rows, combine 3-wide windows with pair sharing, streaming-store a float4.
__device__ __forceinline__ void emit_row(const float* a, const float* mn,
                                         const float* mx,
                                         float* __restrict__ outp) {
    float lo[6], mi[6], hi[6];
    #pragma unroll
    for (int i = 0; i < 6; i++) {
        lo[i] = fminf(a[i], mn[i]);
        hi[i] = fmaxf(a[i], mx[i]);
        mi[i] = fmaxf(mn[i], fminf(a[i], mx[i]));
    }
    float o[4];
    #pragma unroll
    for (int t = 0; t < 2; t++) {
        const int i = 2 * t + 1;
        const float A = fmaxf(lo[i], lo[i + 1]);
        const float B = fminf(hi[i], hi[i + 1]);
        const float n = fminf(mi[i], mi[i + 1]);
        const float m = fmaxf(mi[i], mi[i + 1]);
        o[2 * t]     = med3(fmaxf(A, lo[2 * t]),
                            fmaxf(n, fminf(m, mi[2 * t])),
                            fminf(B, hi[2 * t]));
        o[2 * t + 1] = med3(fmaxf(A, lo[2 * t + 3]),
                            fminf(m, fmaxf(n, mi[2 * t + 3])),
                            fminf(B, hi[2 * t + 3]));
    }
    float4 res; res.x = o[0]; res.y = o[1]; res.z = o[2]; res.w = o[3];
    __stcs(reinterpret_cast<float4*>(outp), res);
}

// Core compute given 6 loaded rows (R10 order). Used by both paths.
__device__ __forceinline__ void compute_strip(
    const float* ra, const float* rb, const float* rc,
    const float* rd, const float* re, const float* rf,
    float* __restrict__ op) {
    float mn[6], mx[6];
    #pragma unroll
    for (int i = 0; i < 6; i++) {
        mn[i] = fminf(rb[i], rc[i]);
        mx[i] = fmaxf(rb[i], rc[i]);
    }
    emit_row(ra, mn, mx, op);
    emit_row(rd, mn, mx, op + W);
    #pragma unroll
    for (int i = 0; i < 6; i++) {
        mn[i] = fminf(rd[i], re[i]);
        mx[i] = fmaxf(rd[i], re[i]);
    }
    emit_row(rc, mn, mx, op + 2 * W);
    emit_row(rf, mn, mx, op + 3 * W);
}

__global__ void __launch_bounds__(128, 10)
median3x3_kernel(const float* __restrict__ x, float* __restrict__ out) {
    const int tid = blockIdx.x * 128 + threadIdx.x;
    const int cb  = (tid & 127) << 2;          // column base (0..508)
    const int sid = tid >> 7;                  // strip id (uniform per block)
    const int y0  = (sid & 127) << 2;          // strip top output row (step 4)
    const int ibase = (sid >> 7) * (H * W);
    const float* img = x + ibase;
    float* oimg = out + ibase;

    const int cl = (cb == 0)     ? 0     : cb - 1;
    const int cr = (cb == W - 4) ? W - 1 : cb + 4;
    const float ml = (cb > 0)     ? 1.0f : 0.0f;
    const float mr = (cb < W - 4) ? 1.0f : 0.0f;

    float ra[6], rb[6], rc[6], rd[6], re[6], rf[6];
    float* op = oimg + y0 * W + cb;

    if (y0 > 0 && y0 < H - 4) {
        // ---- interior strip (126/128): no row masks, immediate offsets ----
        const float* p = img + y0 * W;         // rows y0-1 .. y0+4 = p-W .. p+4W
        load_row<false>(p - W,     cb, cl, cr, ml, mr, 1.0f, ra);
        load_row<false>(p,         cb, cl, cr, ml, mr, 1.0f, rb);
        load_row<false>(p + W,     cb, cl, cr, ml, mr, 1.0f, rc);
        load_row<false>(p + 2 * W, cb, cl, cr, ml, mr, 1.0f, rd);
        load_row<false>(p + 3 * W, cb, cl, cr, ml, mr, 1.0f, re);
        load_row<false>(p + 4 * W, cb, cl, cr, ml, mr, 1.0f, rf);
        compute_strip(ra, rb, rc, rd, re, rf, op);
    } else {
        // ---- boundary strip (2/128): R10's masked/clamped path ----
        const float mt = (y0 > 0)     ? 1.0f : 0.0f;
        const float mb = (y0 < H - 4) ? 1.0f : 0.0f;
        load_row<true >(img + (y0 > 0 ? y0 - 1 : 0) * W, cb, cl, cr, ml, mr, mt, ra);
        load_row<false>(img + (y0    ) * W, cb, cl, cr, ml, mr, 1.0f, rb);
        load_row<false>(img + (y0 + 1) * W, cb, cl, cr, ml, mr, 1.0f, rc);
        load_row<false>(img + (y0 + 2) * W, cb, cl, cr, ml, mr, 1.0f, rd);
        load_row<false>(img + (y0 + 3) * W, cb, cl, cr, ml, mr, 1.0f, re);
        load_row<true >(img + (y0 + 4 < H ? y0 + 4 : H - 1) * W, cb, cl, cr, ml, mr, mb, rf);
        compute_strip(ra, rb, rc, rd, re, rf, op);
    }
}

extern "C" void kernel_launch(void* const* d_in, const int* in_sizes, int n_in,
                              void* d_out, int out_size) {
    const float* x = (const float*)d_in[0];
    float* out = (float*)d_out;

    const int total_threads = (NIMG * H * W) / 16;   // 1,572,864
    const int block = 128;
    const int grid = total_threads / block;           // 12288
    median3x3_kernel<<<grid, block>>>(x, out);
}